// round 16
// baseline (speedup 1.0000x reference)
#include <cuda_runtime.h>
#include <cuda_bf16.h>
#include <cstdint>
#include <cstddef>

#define NN 50000
#define NE 1600000
#define DD 128
#define RR 24
#define BB 8
#define KTOT (BB*DD + DD)     /* 1152 */
#define NR (NN*RR)            /* 1,200,000 */
#define WCF4 (KTOT*DD/4)      /* 36864 float4 in Wc */
#define WCBLK (WCF4/256)      /* 144 blocks convert Wc */

// ---------------- device scratch (no allocations allowed) ----------------
// g_cnt/g_cursor are zero at process start and re-zeroed at the END of every
// kernel_launch (tail of last gemm), so every call does identical work.
__device__ float g_h0[(size_t)NN * DD];
__device__ float g_h1[(size_t)NN * DD];
__device__ float g_A [(size_t)NN * KTOT];
__device__ float g_Wc[(size_t)KTOT * DD];   // [k][n]
__device__ int   g_cnt[NR];
__device__ int   g_seg_start[NR];
__device__ int   g_seg_off[NR];
__device__ int   g_sorted_src[NE];
__device__ int   g_cursor;

// round-to-nearest tf32
__device__ __forceinline__ float tf32r(float x) {
    uint32_t u;
    asm("cvt.rna.tf32.f32 %0, %1;" : "=r"(u) : "f"(x));
    return __uint_as_float(u);
}

__device__ __forceinline__ void cp16(void* smem_ptr, const void* gptr, bool pred) {
    uint32_t s = (uint32_t)__cvta_generic_to_shared(smem_ptr);
    int sz = pred ? 16 : 0;
    asm volatile("cp.async.cg.shared.global [%0], [%1], 16, %2;\n"
                 :: "r"(s), "l"(gptr), "r"(sz));
}
// variant with memory clobber: keeps the ring LDS/cp.async program order
__device__ __forceinline__ void cp16m(void* smem_ptr, const void* gptr) {
    uint32_t s = (uint32_t)__cvta_generic_to_shared(smem_ptr);
    asm volatile("cp.async.cg.shared.global [%0], [%1], 16;\n"
                 :: "r"(s), "l"(gptr) : "memory");
}

// ---------------- setup kernels ----------------

__global__ void k_hist(const int* __restrict__ dst, const int* __restrict__ ety) {
    int e = blockIdx.x * blockDim.x + threadIdx.x;
    if (e < NE) atomicAdd(&g_cnt[dst[e] * RR + ety[e]], 1);
}

__global__ __launch_bounds__(256) void k_seg_assign() {
    __shared__ int wtot[8];
    __shared__ int s_base;
    int i = blockIdx.x * 256 + threadIdx.x;
    int lane = threadIdx.x & 31, wid = threadIdx.x >> 5;
    int c = (i < NR) ? g_cnt[i] : 0;
    int incl = c;
    #pragma unroll
    for (int d = 1; d < 32; d <<= 1) {
        int t = __shfl_up_sync(0xffffffffu, incl, d);
        if (lane >= d) incl += t;
    }
    if (lane == 31) wtot[wid] = incl;
    __syncthreads();
    if (threadIdx.x == 0) {
        int s = 0;
        #pragma unroll
        for (int j = 0; j < 8; j++) { int t = wtot[j]; wtot[j] = s; s += t; }
        s_base = atomicAdd(&g_cursor, s);
    }
    __syncthreads();
    if (i < NR) {
        int off = s_base + wtot[wid] + incl - c;
        g_seg_start[i] = off;
        g_seg_off[i]   = off;
    }
}

__global__ void k_place_embed(const int* __restrict__ src, const int* __restrict__ dst,
                              const int* __restrict__ ety,
                              const int* __restrict__ x, const float4* __restrict__ emb) {
    int e = blockIdx.x * blockDim.x + threadIdx.x;
    if (e < NE) {
        int pos = atomicAdd(&g_seg_off[dst[e] * RR + ety[e]], 1);
        g_sorted_src[pos] = src[e];
    }
    if (e < NN * 32) {
        int n = e >> 5;
        int c = e & 31;
        ((float4*)g_h0)[e] = emb[(size_t)x[n] * 32 + c];
    }
}

// ---------------- aggregation: warp per node, cp.async-ring gather ----------
// Per warp: stage pk = (src | r<<16) in smem; then a depth-7 cp.async pipeline
// streams edge rows h4[src] into a per-warp smem ring (zero register cost for
// in-flight data), consumed via LDS.128 + the round-12 EDGE_FMA block.
#define AGG_D 7      /* prefetch distance */
__global__ __launch_bounds__(256) void k_aggregate(int use_h1, const float* __restrict__ comp,
                                                   const float4* __restrict__ bases4,
                                                   const float4* __restrict__ root4) {
    const float4* __restrict__ h4 = (const float4*)(use_h1 ? g_h1 : g_h0);
    const int* __restrict__ srt = g_sorted_src;

    if (blockIdx.x < WCBLK) {
        int i = blockIdx.x * 256 + threadIdx.x;   // < WCF4 exactly
        float4 v = (i < BB * DD * DD / 4) ? bases4[i] : root4[i - BB * DD * DD / 4];
        v.x = tf32r(v.x); v.y = tf32r(v.y); v.z = tf32r(v.z); v.w = tf32r(v.w);
        ((float4*)g_Wc)[i] = v;
    }

    __shared__ float  s_comp[RR * BB];
    __shared__ int    s_pk[8][128];
    __shared__ float  s_w[8][RR * BB];
    __shared__ float4 s_ring[8][8][32];   // 8 warps x 8 slots x 512B = 32KB
    for (int j = threadIdx.x; j < RR * BB; j += 256) s_comp[j] = comp[j];
    __syncthreads();

    const int lane = threadIdx.x & 31;
    const int wid  = threadIdx.x >> 5;
    const int n = (blockIdx.x * 256 + threadIdx.x) >> 5;   // 6250*8 = NN exactly

    int start_l = 0, cnt_l = 0;
    if (lane < RR) {
        start_l = g_seg_start[n * RR + lane];
        cnt_l   = g_seg_off[n * RR + lane] - start_l;
    }
    int incl = cnt_l;
    #pragma unroll
    for (int d = 1; d < 32; d <<= 1) {
        int t = __shfl_up_sync(0xffffffffu, incl, d);
        if (lane >= d) incl += t;
    }
    const int pos_l = incl - cnt_l;
    const int total = __shfl_sync(0xffffffffu, incl, 31);

    float z[BB][4];
    #pragma unroll
    for (int b = 0; b < BB; b++)
        #pragma unroll
        for (int j = 0; j < 4; j++) z[b][j] = 0.f;

    if (total <= 128) {
        for (int j = 0; j < cnt_l; j++)
            s_pk[wid][pos_l + j] = __ldg(&srt[start_l + j]) | (lane << 16);
        if (lane < RR) {
            float invc = (cnt_l > 0) ? 1.0f / (float)cnt_l : 0.0f;
            #pragma unroll
            for (int b = 0; b < BB; b++)
                s_w[wid][lane * BB + b] = s_comp[lane * BB + b] * invc;
        }
        __syncwarp();

        #define EDGE_FMA(P, V)                                                     \
        do {                                                                       \
            const float4* wq = (const float4*)&s_w[wid][((P) >> 16) * BB];         \
            float4 wa = wq[0], wb = wq[1];                                         \
            z[0][0] = fmaf(wa.x, (V).x, z[0][0]); z[0][1] = fmaf(wa.x, (V).y, z[0][1]); \
            z[0][2] = fmaf(wa.x, (V).z, z[0][2]); z[0][3] = fmaf(wa.x, (V).w, z[0][3]); \
            z[1][0] = fmaf(wa.y, (V).x, z[1][0]); z[1][1] = fmaf(wa.y, (V).y, z[1][1]); \
            z[1][2] = fmaf(wa.y, (V).z, z[1][2]); z[1][3] = fmaf(wa.y, (V).w, z[1][3]); \
            z[2][0] = fmaf(wa.z, (V).x, z[2][0]); z[2][1] = fmaf(wa.z, (V).y, z[2][1]); \
            z[2][2] = fmaf(wa.z, (V).z, z[2][2]); z[2][3] = fmaf(wa.z, (V).w, z[2][3]); \
            z[3][0] = fmaf(wa.w, (V).x, z[3][0]); z[3][1] = fmaf(wa.w, (V).y, z[3][1]); \
            z[3][2] = fmaf(wa.w, (V).z, z[3][2]); z[3][3] = fmaf(wa.w, (V).w, z[3][3]); \
            z[4][0] = fmaf(wb.x, (V).x, z[4][0]); z[4][1] = fmaf(wb.x, (V).y, z[4][1]); \
            z[4][2] = fmaf(wb.x, (V).z, z[4][2]); z[4][3] = fmaf(wb.x, (V).w, z[4][3]); \
            z[5][0] = fmaf(wb.y, (V).x, z[5][0]); z[5][1] = fmaf(wb.y, (V).y, z[5][1]); \
            z[5][2] = fmaf(wb.y, (V).z, z[5][2]); z[5][3] = fmaf(wb.y, (V).w, z[5][3]); \
            z[6][0] = fmaf(wb.z, (V).x, z[6][0]); z[6][1] = fmaf(wb.z, (V).y, z[6][1]); \
            z[6][2] = fmaf(wb.z, (V).z, z[6][2]); z[6][3] = fmaf(wb.z, (V).w, z[6][3]); \
            z[7][0] = fmaf(wb.w, (V).x, z[7][0]); z[7][1] = fmaf(wb.w, (V).y, z[7][1]); \
            z[7][2] = fmaf(wb.w, (V).z, z[7][2]); z[7][3] = fmaf(wb.w, (V).w, z[7][3]); \
        } while (0)

        // prologue: AGG_D commit groups (empty commits keep accounting uniform)
        #pragma unroll
        for (int j = 0; j < AGG_D; j++) {
            if (j < total) {
                int s0 = s_pk[wid][j] & 0xFFFF;
                cp16m(&s_ring[wid][j][lane], &h4[s0 * 32 + lane]);
            }
            asm volatile("cp.async.commit_group;" ::: "memory");
        }
        for (int k = 0; k < total; k++) {
            asm volatile("cp.async.wait_group %0;" :: "n"(AGG_D - 1) : "memory");
            int p = s_pk[wid][k];
            float4 v = s_ring[wid][k & 7][lane];
            int kp = k + AGG_D;
            if (kp < total) {
                int s1 = s_pk[wid][kp] & 0xFFFF;
                cp16m(&s_ring[wid][kp & 7][lane], &h4[s1 * 32 + lane]);
            }
            asm volatile("cp.async.commit_group;" ::: "memory");
            EDGE_FMA(p, v);
        }
        #undef EDGE_FMA
    } else {
        // fallback: per-segment loop (extremely high-degree node)
        for (int r = 0; r < RR; r++) {
            int c  = __shfl_sync(0xffffffffu, cnt_l, r);
            if (c == 0) continue;
            int e0 = __shfl_sync(0xffffffffu, start_l, r);
            int e1 = e0 + c;
            float4 a0 = make_float4(0.f, 0.f, 0.f, 0.f);
            float4 a1 = a0, a2 = a0, a3 = a0;
            int e = e0;
            for (; e + 3 < e1; e += 4) {
                float4 v0 = __ldg(&h4[__ldg(&srt[e])     * 32 + lane]);
                float4 v1 = __ldg(&h4[__ldg(&srt[e + 1]) * 32 + lane]);
                float4 v2 = __ldg(&h4[__ldg(&srt[e + 2]) * 32 + lane]);
                float4 v3 = __ldg(&h4[__ldg(&srt[e + 3]) * 32 + lane]);
                a0.x += v0.x; a0.y += v0.y; a0.z += v0.z; a0.w += v0.w;
                a1.x += v1.x; a1.y += v1.y; a1.z += v1.z; a1.w += v1.w;
                a2.x += v2.x; a2.y += v2.y; a2.z += v2.z; a2.w += v2.w;
                a3.x += v3.x; a3.y += v3.y; a3.z += v3.z; a3.w += v3.w;
            }
            for (; e < e1; e++) {
                float4 v0 = __ldg(&h4[__ldg(&srt[e]) * 32 + lane]);
                a0.x += v0.x; a0.y += v0.y; a0.z += v0.z; a0.w += v0.w;
            }
            float inv = 1.0f / (float)c;
            float m0 = ((a0.x + a1.x) + (a2.x + a3.x)) * inv;
            float m1 = ((a0.y + a1.y) + (a2.y + a3.y)) * inv;
            float m2 = ((a0.z + a1.z) + (a2.z + a3.z)) * inv;
            float m3 = ((a0.w + a1.w) + (a2.w + a3.w)) * inv;
            #pragma unroll
            for (int b = 0; b < BB; b++) {
                float w = s_comp[r * BB + b];
                z[b][0] = fmaf(w, m0, z[b][0]);
                z[b][1] = fmaf(w, m1, z[b][1]);
                z[b][2] = fmaf(w, m2, z[b][2]);
                z[b][3] = fmaf(w, m3, z[b][3]);
            }
        }
    }

    float4* Arow = (float4*)&g_A[(size_t)n * KTOT];
    #pragma unroll
    for (int b = 0; b < BB; b++) {
        float4 v;
        v.x = tf32r(z[b][0]); v.y = tf32r(z[b][1]);
        v.z = tf32r(z[b][2]); v.w = tf32r(z[b][3]);
        Arow[b * 32 + lane] = v;
    }
    float4 hv = __ldg(&h4[n * 32 + lane]);
    hv.x = tf32r(hv.x); hv.y = tf32r(hv.y); hv.z = tf32r(hv.z); hv.w = tf32r(hv.w);
    Arow[BB * 32 + lane] = hv;
}

// ---------------- tf32 tensor-core GEMM (BM=64, near-single-wave) -----------
// out[N,128] = g_A[N,1152] @ g_Wc[1152,128] + bias (optional relu)
// BM=64, BN=128, BK=16, 128 threads (4 warps, warp tile 32x64), 2-stage
// cp.async, 27.6KB smem, __launch_bounds__(128,5): 5 blocks/SM -> 740 resident
// slots vs 782 blocks = 1.06 waves (was 391/296 = heavy tail).
#define GBM 64
#define GBK 16
#define NITER (KTOT / GBK)   /* 72 */

__global__ __launch_bounds__(128, 5) void k_gemm_tc(const float* __restrict__ bias,
                                                    float* __restrict__ outp, int relu,
                                                    int zero_next) {
    if (zero_next) {
        for (int i = blockIdx.x * 128 + threadIdx.x; i < NR / 4; i += gridDim.x * 128)
            ((int4*)g_cnt)[i] = make_int4(0, 0, 0, 0);
        if (blockIdx.x == 0 && threadIdx.x == 0) g_cursor = 0;
    }

    __shared__ float As[2][GBM][20];
    __shared__ float Bs[2][GBK][136];

    const int tid  = threadIdx.x;
    const int wid  = tid >> 5;
    const int lane = tid & 31;
    const int g    = lane >> 2;
    const int q    = lane & 3;
    const int warp_m = (wid >> 1) * 32;
    const int warp_n = (wid & 1) * 64;
    const int row0 = blockIdx.x * GBM;

    float acc[2][8][4];
    #pragma unroll
    for (int mi = 0; mi < 2; mi++)
        #pragma unroll
        for (int nj = 0; nj < 8; nj++)
            #pragma unroll
            for (int k = 0; k < 4; k++) acc[mi][nj][k] = 0.f;

    // A tile: 64x16 floats = 256 float4; 2 per thread
    // B tile: 16x128 floats = 512 float4; 4 per thread
    #define LOAD_TILES(K0, BUF)                                                   \
    do {                                                                          \
        _Pragma("unroll")                                                         \
        for (int j = 0; j < 2; j++) {                                             \
            int idx = tid + j * 128;                                              \
            int ar = idx >> 2, ac = (idx & 3) * 4;                                \
            bool ok = (row0 + ar) < NN;                                           \
            const float* src = ok ? &g_A[(size_t)(row0 + ar) * KTOT + (K0) + ac]  \
                                  : &g_A[0];                                      \
            cp16(&As[BUF][ar][ac], src, ok);                                      \
        }                                                                         \
        _Pragma("unroll")                                                         \
        for (int j = 0; j < 4; j++) {                                             \
            int idx = tid + j * 128;                                              \
            int br = idx >> 5, bc = (idx & 31) * 4;                               \
            cp16(&Bs[BUF][br][bc], &g_Wc[(size_t)((K0) + br) * DD + bc], true);   \
        }                                                                         \
    } while (0)

    LOAD_TILES(0, 0);
    asm volatile("cp.async.commit_group;");

    for (int it = 0; it < NITER; it++) {
        const int cur = it & 1;
        const int nxt = cur ^ 1;
        if (it + 1 < NITER) LOAD_TILES((it + 1) * GBK, nxt);
        asm volatile("cp.async.commit_group;");
        asm volatile("cp.async.wait_group 1;");
        __syncthreads();

        #pragma unroll
        for (int s = 0; s < 2; s++) {
            const int kb = s * 8;
            uint32_t af[2][4];
            uint32_t bf[8][2];
            #pragma unroll
            for (int mi = 0; mi < 2; mi++) {
                int m = warp_m + mi * 16 + g;
                af[mi][0] = __float_as_uint(As[cur][m][kb + q]);
                af[mi][1] = __float_as_uint(As[cur][m + 8][kb + q]);
                af[mi][2] = __float_as_uint(As[cur][m][kb + q + 4]);
                af[mi][3] = __float_as_uint(As[cur][m + 8][kb + q + 4]);
            }
            #pragma unroll
            for (int nj = 0; nj < 8; nj++) {
                int n = warp_n + nj * 8 + g;
                bf[nj][0] = __float_as_uint(Bs[cur][kb + q][n]);
                bf[nj][1] = __float_as_uint(Bs[cur][kb + q + 4][n]);
            }
            #pragma unroll
            for (int mi = 0; mi < 2; mi++)
                #pragma unroll
                for (int nj = 0; nj < 8; nj++) {
                    asm volatile(
                        "mma.sync.aligned.m16n8k8.row.col.f32.tf32.tf32.f32 "
                        "{%0,%1,%2,%3}, {%4,%5,%6,%7}, {%8,%9}, {%0,%1,%2,%3};\n"
                        : "+f"(acc[mi][nj][0]), "+f"(acc[mi][nj][1]),
                          "+f"(acc[mi][nj][2]), "+f"(acc[mi][nj][3])
                        : "r"(af[mi][0]), "r"(af[mi][1]), "r"(af[mi][2]), "r"(af[mi][3]),
                          "r"(bf[nj][0]), "r"(bf[nj][1]));
                }
        }
        __syncthreads();
    }

    float* dstb = outp ? outp : g_h1;
    #pragma unroll
    for (int mi = 0; mi < 2; mi++) {
        #pragma unroll
        for (int nj = 0; nj < 8; nj++) {
            int c  = warp_n + nj * 8 + q * 2;
            float b0 = __ldg(&bias[c]);
            float b1 = __ldg(&bias[c + 1]);
            int ra = row0 + warp_m + mi * 16 + g;
            int rb = ra + 8;
            float2 v0, v1;
            v0.x = acc[mi][nj][0] + b0; v0.y = acc[mi][nj][1] + b1;
            v1.x = acc[mi][nj][2] + b0; v1.y = acc[mi][nj][3] + b1;
            if (relu) {
                v0.x = fmaxf(v0.x, 0.f); v0.y = fmaxf(v0.y, 0.f);
                v1.x = fmaxf(v1.x, 0.f); v1.y = fmaxf(v1.y, 0.f);
            }
            if (ra < NN) *(float2*)&dstb[(size_t)ra * DD + c] = v0;
            if (rb < NN) *(float2*)&dstb[(size_t)rb * DD + c] = v1;
        }
    }
}

// ---------------- host launch ----------------
extern "C" void kernel_launch(void* const* d_in, const int* in_sizes, int n_in,
                              void* d_out, int out_size) {
    const int*   x      = (const int*)  d_in[0];
    const int*   ei     = (const int*)  d_in[1];
    const int*   ety    = (const int*)  d_in[2];
    const float* emb    = (const float*)d_in[3];
    const float* comp1  = (const float*)d_in[4];
    const float* bases1 = (const float*)d_in[5];
    const float* root1  = (const float*)d_in[6];
    const float* bias1  = (const float*)d_in[7];
    const float* comp2  = (const float*)d_in[8];
    const float* bases2 = (const float*)d_in[9];
    const float* root2  = (const float*)d_in[10];
    const float* bias2  = (const float*)d_in[11];
    const int* src = ei;
    const int* dst = ei + NE;
    float* out = (float*)d_out;

    const int gemm_blocks = (NN + GBM - 1) / GBM;   // 782
    const int agg_blocks  = NN / 8;                 // 6250

    k_hist       <<<(NE + 255) / 256, 256>>>(dst, ety);                 // #1
    k_seg_assign <<<(NR + 255) / 256, 256>>>();                         // #2
    k_place_embed<<<NE / 256, 256>>>(src, dst, ety, x, (const float4*)emb); // #3
    k_aggregate  <<<agg_blocks, 256>>>(0, comp1,                        // #4 (profiled)
                                       (const float4*)bases1, (const float4*)root1);
    k_gemm_tc    <<<gemm_blocks, 128>>>(bias1, nullptr, 1, 0);          // #5
    k_aggregate  <<<agg_blocks, 256>>>(1, comp2,                        // #6
                                       (const float4*)bases2, (const float4*)root2);
    k_gemm_tc    <<<gemm_blocks, 128>>>(bias2, out, 0, 1);              // #7
}

// round 17
// speedup vs baseline: 1.3293x; 1.3293x over previous
#include <cuda_runtime.h>
#include <cuda_fp16.h>
#include <cstdint>
#include <cstddef>

#define NN 50000
#define NE 1600000
#define DD 128
#define RR 24
#define BB 8
#define KTOT (BB*DD + DD)     /* 1152 */
#define NR (NN*RR)            /* 1,200,000 */
#define WCQ (KTOT*DD/4)       /* 36864 4-half groups in WcT */
#define WCBLK (WCQ/256)       /* 144 blocks convert WcT */

// ---------------- device scratch (no allocations allowed) ----------------
// g_cnt/g_cursor are zero at process start and re-zeroed at the END of every
// kernel_launch (tail of last gemm), so every call does identical work.
__device__ __half g_h0h[(size_t)NN * DD];        // fp16 h (layer-1 input)
__device__ __half g_h1h[(size_t)NN * DD];        // fp16 relu(out1)
__device__ __half g_Ah [(size_t)NN * KTOT];      // fp16 GEMM LHS
__device__ __half g_WcT[(size_t)DD * KTOT];      // fp16 B, [n][k] (col-major for mma)
__device__ int    g_cnt[NR];
__device__ int    g_seg_start[NR];
__device__ int    g_seg_off[NR];
__device__ int    g_sorted_src[NE];
__device__ int    g_cursor;

__device__ __forceinline__ void cp16(void* smem_ptr, const void* gptr, bool pred) {
    uint32_t s = (uint32_t)__cvta_generic_to_shared(smem_ptr);
    int sz = pred ? 16 : 0;
    asm volatile("cp.async.cg.shared.global [%0], [%1], 16, %2;\n"
                 :: "r"(s), "l"(gptr), "r"(sz));
}

// ---------------- setup kernels ----------------

__global__ void k_hist(const int* __restrict__ dst, const int* __restrict__ ety) {
    int e = blockIdx.x * blockDim.x + threadIdx.x;
    if (e < NE) atomicAdd(&g_cnt[dst[e] * RR + ety[e]], 1);
}

__global__ __launch_bounds__(256) void k_seg_assign() {
    __shared__ int wtot[8];
    __shared__ int s_base;
    int i = blockIdx.x * 256 + threadIdx.x;
    int lane = threadIdx.x & 31, wid = threadIdx.x >> 5;
    int c = (i < NR) ? g_cnt[i] : 0;
    int incl = c;
    #pragma unroll
    for (int d = 1; d < 32; d <<= 1) {
        int t = __shfl_up_sync(0xffffffffu, incl, d);
        if (lane >= d) incl += t;
    }
    if (lane == 31) wtot[wid] = incl;
    __syncthreads();
    if (threadIdx.x == 0) {
        int s = 0;
        #pragma unroll
        for (int j = 0; j < 8; j++) { int t = wtot[j]; wtot[j] = s; s += t; }
        s_base = atomicAdd(&g_cursor, s);
    }
    __syncthreads();
    if (i < NR) {
        int off = s_base + wtot[wid] + incl - c;
        g_seg_start[i] = off;
        g_seg_off[i]   = off;
    }
}

// place edges; ALSO embedding gather fp32 -> fp16 (both exactly 1.6M threads).
__global__ void k_place_embed(const int* __restrict__ src, const int* __restrict__ dst,
                              const int* __restrict__ ety,
                              const int* __restrict__ x, const float4* __restrict__ emb) {
    int e = blockIdx.x * blockDim.x + threadIdx.x;
    if (e < NE) {
        int pos = atomicAdd(&g_seg_off[dst[e] * RR + ety[e]], 1);
        g_sorted_src[pos] = src[e];
    }
    if (e < NN * 32) {     // e indexes 4-float groups: n = e>>5, c = e&31
        int n = e >> 5;
        int c = e & 31;
        float4 v = emb[(size_t)x[n] * 32 + c];
        __half2 a = __floats2half2_rn(v.x, v.y);
        __half2 b = __floats2half2_rn(v.z, v.w);
        uint2 w;
        w.x = *(uint32_t*)&a;
        w.y = *(uint32_t*)&b;
        ((uint2*)g_h0h)[e] = w;
    }
}

// ---------------- aggregation: warp per node, flat edge loop, fp16 h --------
// First WCBLK blocks also build WcT[n][k] = fp16(W[k][n]).
__global__ __launch_bounds__(256) void k_aggregate(int use_h1, const float* __restrict__ comp,
                                                   const float* __restrict__ basesf,
                                                   const float* __restrict__ rootf) {
    const __half* __restrict__ hp = use_h1 ? g_h1h : g_h0h;
    const int* __restrict__ srt = g_sorted_src;

    if (blockIdx.x < WCBLK) {
        int i = blockIdx.x * 256 + threadIdx.x;   // 4-half group in WcT, < WCQ
        int n  = i / (KTOT / 4);
        int k0 = (i % (KTOT / 4)) * 4;
        float f[4];
        #pragma unroll
        for (int j = 0; j < 4; j++) {
            int k = k0 + j;
            f[j] = (k < BB * DD) ? basesf[(size_t)k * DD + n]
                                 : rootf[(size_t)(k - BB * DD) * DD + n];
        }
        __half2 a = __floats2half2_rn(f[0], f[1]);
        __half2 b = __floats2half2_rn(f[2], f[3]);
        uint2 w;
        w.x = *(uint32_t*)&a;
        w.y = *(uint32_t*)&b;
        ((uint2*)g_WcT)[i] = w;
    }

    __shared__ float s_comp[RR * BB];
    __shared__ int   s_pk[8][128];
    __shared__ float s_w[8][RR * BB];
    for (int j = threadIdx.x; j < RR * BB; j += 256) s_comp[j] = comp[j];
    __syncthreads();

    const int lane = threadIdx.x & 31;
    const int wid  = threadIdx.x >> 5;
    const int n = (blockIdx.x * 256 + threadIdx.x) >> 5;   // 6250*8 = NN exactly

    int start_l = 0, cnt_l = 0;
    if (lane < RR) {
        start_l = g_seg_start[n * RR + lane];
        cnt_l   = g_seg_off[n * RR + lane] - start_l;
    }
    int incl = cnt_l;
    #pragma unroll
    for (int d = 1; d < 32; d <<= 1) {
        int t = __shfl_up_sync(0xffffffffu, incl, d);
        if (lane >= d) incl += t;
    }
    const int pos_l = incl - cnt_l;
    const int total = __shfl_sync(0xffffffffu, incl, 31);

    float z[BB][4];
    #pragma unroll
    for (int b = 0; b < BB; b++)
        #pragma unroll
        for (int j = 0; j < 4; j++) z[b][j] = 0.f;

    // gather one edge row slice (8B = 4 halfs) and convert to float4
    #define GATHER(S, V)                                                           \
    do {                                                                           \
        uint2 raw = __ldg((const uint2*)(hp + (size_t)(S) * DD) + lane);           \
        float2 f01 = __half22float2(*(__half2*)&raw.x);                            \
        float2 f23 = __half22float2(*(__half2*)&raw.y);                            \
        (V).x = f01.x; (V).y = f01.y; (V).z = f23.x; (V).w = f23.y;                \
    } while (0)

    if (total <= 128) {
        for (int j = 0; j < cnt_l; j++)
            s_pk[wid][pos_l + j] = __ldg(&srt[start_l + j]) | (lane << 16);
        if (lane < RR) {
            float invc = (cnt_l > 0) ? 1.0f / (float)cnt_l : 0.0f;
            #pragma unroll
            for (int b = 0; b < BB; b++)
                s_w[wid][lane * BB + b] = s_comp[lane * BB + b] * invc;
        }
        __syncwarp();

        #define EDGE_FMA(P, V)                                                     \
        do {                                                                       \
            const float4* wq = (const float4*)&s_w[wid][((P) >> 16) * BB];         \
            float4 wa = wq[0], wb = wq[1];                                         \
            z[0][0] = fmaf(wa.x, (V).x, z[0][0]); z[0][1] = fmaf(wa.x, (V).y, z[0][1]); \
            z[0][2] = fmaf(wa.x, (V).z, z[0][2]); z[0][3] = fmaf(wa.x, (V).w, z[0][3]); \
            z[1][0] = fmaf(wa.y, (V).x, z[1][0]); z[1][1] = fmaf(wa.y, (V).y, z[1][1]); \
            z[1][2] = fmaf(wa.y, (V).z, z[1][2]); z[1][3] = fmaf(wa.y, (V).w, z[1][3]); \
            z[2][0] = fmaf(wa.z, (V).x, z[2][0]); z[2][1] = fmaf(wa.z, (V).y, z[2][1]); \
            z[2][2] = fmaf(wa.z, (V).z, z[2][2]); z[2][3] = fmaf(wa.z, (V).w, z[2][3]); \
            z[3][0] = fmaf(wa.w, (V).x, z[3][0]); z[3][1] = fmaf(wa.w, (V).y, z[3][1]); \
            z[3][2] = fmaf(wa.w, (V).z, z[3][2]); z[3][3] = fmaf(wa.w, (V).w, z[3][3]); \
            z[4][0] = fmaf(wb.x, (V).x, z[4][0]); z[4][1] = fmaf(wb.x, (V).y, z[4][1]); \
            z[4][2] = fmaf(wb.x, (V).z, z[4][2]); z[4][3] = fmaf(wb.x, (V).w, z[4][3]); \
            z[5][0] = fmaf(wb.y, (V).x, z[5][0]); z[5][1] = fmaf(wb.y, (V).y, z[5][1]); \
            z[5][2] = fmaf(wb.y, (V).z, z[5][2]); z[5][3] = fmaf(wb.y, (V).w, z[5][3]); \
            z[6][0] = fmaf(wb.z, (V).x, z[6][0]); z[6][1] = fmaf(wb.z, (V).y, z[6][1]); \
            z[6][2] = fmaf(wb.z, (V).z, z[6][2]); z[6][3] = fmaf(wb.z, (V).w, z[6][3]); \
            z[7][0] = fmaf(wb.w, (V).x, z[7][0]); z[7][1] = fmaf(wb.w, (V).y, z[7][1]); \
            z[7][2] = fmaf(wb.w, (V).z, z[7][2]); z[7][3] = fmaf(wb.w, (V).w, z[7][3]); \
        } while (0)

        int k = 0;
        for (; k + 3 < total; k += 4) {
            int4 pk = *(const int4*)&s_pk[wid][k];
            float4 v0, v1, v2, v3;
            GATHER(pk.x & 0xFFFF, v0);
            GATHER(pk.y & 0xFFFF, v1);
            GATHER(pk.z & 0xFFFF, v2);
            GATHER(pk.w & 0xFFFF, v3);
            EDGE_FMA(pk.x, v0);
            EDGE_FMA(pk.y, v1);
            EDGE_FMA(pk.z, v2);
            EDGE_FMA(pk.w, v3);
        }
        for (; k < total; k++) {
            int p0 = s_pk[wid][k];
            float4 v0;
            GATHER(p0 & 0xFFFF, v0);
            EDGE_FMA(p0, v0);
        }
        #undef EDGE_FMA
    } else {
        // fallback: per-segment loop (extremely high-degree node)
        for (int r = 0; r < RR; r++) {
            int c  = __shfl_sync(0xffffffffu, cnt_l, r);
            if (c == 0) continue;
            int e0 = __shfl_sync(0xffffffffu, start_l, r);
            int e1 = e0 + c;
            float4 a0 = make_float4(0.f, 0.f, 0.f, 0.f);
            float4 a1 = a0, a2 = a0, a3 = a0;
            int e = e0;
            for (; e + 3 < e1; e += 4) {
                float4 v0, v1, v2, v3;
                GATHER(__ldg(&srt[e]),     v0);
                GATHER(__ldg(&srt[e + 1]), v1);
                GATHER(__ldg(&srt[e + 2]), v2);
                GATHER(__ldg(&srt[e + 3]), v3);
                a0.x += v0.x; a0.y += v0.y; a0.z += v0.z; a0.w += v0.w;
                a1.x += v1.x; a1.y += v1.y; a1.z += v1.z; a1.w += v1.w;
                a2.x += v2.x; a2.y += v2.y; a2.z += v2.z; a2.w += v2.w;
                a3.x += v3.x; a3.y += v3.y; a3.z += v3.z; a3.w += v3.w;
            }
            for (; e < e1; e++) {
                float4 v0;
                GATHER(__ldg(&srt[e]), v0);
                a0.x += v0.x; a0.y += v0.y; a0.z += v0.z; a0.w += v0.w;
            }
            float inv = 1.0f / (float)c;
            float m0 = ((a0.x + a1.x) + (a2.x + a3.x)) * inv;
            float m1 = ((a0.y + a1.y) + (a2.y + a3.y)) * inv;
            float m2 = ((a0.z + a1.z) + (a2.z + a3.z)) * inv;
            float m3 = ((a0.w + a1.w) + (a2.w + a3.w)) * inv;
            #pragma unroll
            for (int b = 0; b < BB; b++) {
                float w = s_comp[r * BB + b];
                z[b][0] = fmaf(w, m0, z[b][0]);
                z[b][1] = fmaf(w, m1, z[b][1]);
                z[b][2] = fmaf(w, m2, z[b][2]);
                z[b][3] = fmaf(w, m3, z[b][3]);
            }
        }
    }
    #undef GATHER

    // write A row: 8 Z blocks (fp16) + h append (copy, already fp16)
    uint2* Arow = (uint2*)(g_Ah + (size_t)n * KTOT);   // 8B groups, lane*... per block
    #pragma unroll
    for (int b = 0; b < BB; b++) {
        __half2 p0 = __floats2half2_rn(z[b][0], z[b][1]);
        __half2 p1 = __floats2half2_rn(z[b][2], z[b][3]);
        uint2 w;
        w.x = *(uint32_t*)&p0;
        w.y = *(uint32_t*)&p1;
        Arow[b * 32 + lane] = w;
    }
    uint2 hv = __ldg((const uint2*)(hp + (size_t)n * DD) + lane);
    Arow[BB * 32 + lane] = hv;
}

// ---------------- fp16 tensor-core GEMM (m16n8k16) --------------------------
// out[N,128] = A[N,1152] @ WcT^T + bias (optional relu)
// BM=128, BN=128, BK=32 halfs, 256 threads (8 warps, warp tile 32x64),
// 4-stage cp.async, dynamic smem. Smem rows padded to 80B (conflict-free).
#define GBM 128
#define BKH 32
#define NITER (KTOT / BKH)     /* 36 */
#define ROWB 80                /* bytes per padded smem row (64B data) */
#define STG_BYTES (2 * 128 * ROWB)   /* A rows + B rows = 20480 */
#define GSTG 4
#define GEMM_SMEM (GSTG * STG_BYTES) /* 81920 */

__global__ __launch_bounds__(256, 2) void k_gemm_tc(const float* __restrict__ bias,
                                                    float* __restrict__ outp, int relu,
                                                    int zero_next) {
    if (zero_next) {
        for (int i = blockIdx.x * 256 + threadIdx.x; i < NR / 4; i += gridDim.x * 256)
            ((int4*)g_cnt)[i] = make_int4(0, 0, 0, 0);
        if (blockIdx.x == 0 && threadIdx.x == 0) g_cursor = 0;
    }

    extern __shared__ char smem[];

    const int tid  = threadIdx.x;
    const int wid  = tid >> 5;
    const int lane = tid & 31;
    const int g    = lane >> 2;
    const int q    = lane & 3;
    const int warp_m = (wid >> 1) * 32;
    const int warp_n = (wid & 1) * 64;
    const int row0 = blockIdx.x * GBM;

    float acc[2][8][4];
    #pragma unroll
    for (int mi = 0; mi < 2; mi++)
        #pragma unroll
        for (int nj = 0; nj < 8; nj++)
            #pragma unroll
            for (int k = 0; k < 4; k++) acc[mi][nj][k] = 0.f;

    // stage S: A rows at S*STG_BYTES + r*ROWB; B rows at S*STG_BYTES + 128*ROWB + n*ROWB
    // A tile: 128 rows x 64B = 512 16B chunks; B tile same. 2 chunks each per thread.
    #define LOAD_TILES(C, S)                                                       \
    do {                                                                           \
        _Pragma("unroll")                                                          \
        for (int j = 0; j < 2; j++) {                                              \
            int idx = tid + j * 256;                                               \
            int r = idx >> 2, c16 = idx & 3;                                       \
            bool ok = (row0 + r) < NN;                                             \
            const __half* sa = ok ? &g_Ah[(size_t)(row0 + r) * KTOT + (C) * BKH + c16 * 8] \
                                  : &g_Ah[0];                                      \
            cp16(smem + (S) * STG_BYTES + r * ROWB + c16 * 16, sa, ok);            \
            cp16(smem + (S) * STG_BYTES + 128 * ROWB + r * ROWB + c16 * 16,        \
                 &g_WcT[(size_t)r * KTOT + (C) * BKH + c16 * 8], true);            \
        }                                                                          \
    } while (0)

    #pragma unroll
    for (int p = 0; p < GSTG - 1; p++) {
        LOAD_TILES(p, p);
        asm volatile("cp.async.commit_group;");
    }

    for (int it = 0; it < NITER; it++) {
        if (it + GSTG - 1 < NITER) LOAD_TILES(it + GSTG - 1, (it + GSTG - 1) & (GSTG - 1));
        asm volatile("cp.async.commit_group;");
        asm volatile("cp.async.wait_group 3;");
        __syncthreads();

        const int cur = it & (GSTG - 1);
        const char* Ab = smem + cur * STG_BYTES;
        const char* Bb = Ab + 128 * ROWB;

        #pragma unroll
        for (int kh = 0; kh < 2; kh++) {
            const int koff = kh * 32;     // bytes: 16 halfs per k16 step
            uint32_t af[2][4];
            uint32_t bf[8][2];
            #pragma unroll
            for (int mi = 0; mi < 2; mi++) {
                int m = warp_m + mi * 16 + g;
                af[mi][0] = *(const uint32_t*)(Ab + m * ROWB + koff + q * 4);
                af[mi][1] = *(const uint32_t*)(Ab + (m + 8) * ROWB + koff + q * 4);
                af[mi][2] = *(const uint32_t*)(Ab + m * ROWB + koff + q * 4 + 16);
                af[mi][3] = *(const uint32_t*)(Ab + (m + 8) * ROWB + koff + q * 4 + 16);
            }
            #pragma unroll
            for (int nj = 0; nj < 8; nj++) {
                int n = warp_n + nj * 8 + g;
                bf[nj][0] = *(const uint32_t*)(Bb + n * ROWB + koff + q * 4);
                bf[nj][1] = *(const uint32_t*)(Bb + n * ROWB + koff + q * 4 + 16);
            }
            #pragma unroll
            for (int mi = 0; mi < 2; mi++)
                #pragma unroll
                for (int nj = 0; nj < 8; nj++) {
                    asm volatile(
                        "mma.sync.aligned.m16n8k16.row.col.f32.f16.f16.f32 "
                        "{%0,%1,%2,%3}, {%4,%5,%6,%7}, {%8,%9}, {%0,%1,%2,%3};\n"
                        : "+f"(acc[mi][nj][0]), "+f"(acc[mi][nj][1]),
                          "+f"(acc[mi][nj][2]), "+f"(acc[mi][nj][3])
                        : "r"(af[mi][0]), "r"(af[mi][1]), "r"(af[mi][2]), "r"(af[mi][3]),
                          "r"(bf[nj][0]), "r"(bf[nj][1]));
                }
        }
        __syncthreads();
    }

    #pragma unroll
    for (int mi = 0; mi < 2; mi++) {
        #pragma unroll
        for (int nj = 0; nj < 8; nj++) {
            int c  = warp_n + nj * 8 + q * 2;
            float b0 = __ldg(&bias[c]);
            float b1 = __ldg(&bias[c + 1]);
            int ra = row0 + warp_m + mi * 16 + g;
            int rb = ra + 8;
            float2 v0, v1;
            v0.x = acc[mi][nj][0] + b0; v0.y = acc[mi][nj][1] + b1;
            v1.x = acc[mi][nj][2] + b0; v1.y = acc[mi][nj][3] + b1;
            if (relu) {
                v0.x = fmaxf(v0.x, 0.f); v0.y = fmaxf(v0.y, 0.f);
                v1.x = fmaxf(v1.x, 0.f); v1.y = fmaxf(v1.y, 0.f);
            }
            if (outp) {
                if (ra < NN) *(float2*)&outp[(size_t)ra * DD + c] = v0;
                if (rb < NN) *(float2*)&outp[(size_t)rb * DD + c] = v1;
            } else {
                __half2 h0 = __floats2half2_rn(v0.x, v0.y);
                __half2 h1 = __floats2half2_rn(v1.x, v1.y);
                if (ra < NN) *(uint32_t*)&g_h1h[(size_t)ra * DD + c] = *(uint32_t*)&h0;
                if (rb < NN) *(uint32_t*)&g_h1h[(size_t)rb * DD + c] = *(uint32_t*)&h1;
            }
        }
    }
}

// ---------------- host launch ----------------
extern "C" void kernel_launch(void* const* d_in, const int* in_sizes, int n_in,
                              void* d_out, int out_size) {
    const int*   x      = (const int*)  d_in[0];
    const int*   ei     = (const int*)  d_in[1];
    const int*   ety    = (const int*)  d_in[2];
    const float* emb    = (const float*)d_in[3];
    const float* comp1  = (const float*)d_in[4];
    const float* bases1 = (const float*)d_in[5];
    const float* root1  = (const float*)d_in[6];
    const float* bias1  = (const float*)d_in[7];
    const float* comp2  = (const float*)d_in[8];
    const float* bases2 = (const float*)d_in[9];
    const float* root2  = (const float*)d_in[10];
    const float* bias2  = (const float*)d_in[11];
    const int* src = ei;
    const int* dst = ei + NE;
    float* out = (float*)d_out;

    cudaFuncSetAttribute(k_gemm_tc, cudaFuncAttributeMaxDynamicSharedMemorySize,
                         GEMM_SMEM);

    const int gemm_blocks = (NN + GBM - 1) / GBM;   // 391
    const int agg_blocks  = NN / 8;                 // 6250

    k_hist       <<<(NE + 255) / 256, 256>>>(dst, ety);                 // #1
    k_seg_assign <<<(NR + 255) / 256, 256>>>();                         // #2
    k_place_embed<<<NE / 256, 256>>>(src, dst, ety, x, (const float4*)emb); // #3
    k_aggregate  <<<agg_blocks, 256>>>(0, comp1, bases1, root1);        // #4 (profiled)
    k_gemm_tc    <<<gemm_blocks, 256, GEMM_SMEM>>>(bias1, nullptr, 1, 0);   // #5
    k_aggregate  <<<agg_blocks, 256>>>(1, comp2, bases2, root2);        // #6
    k_gemm_tc    <<<gemm_blocks, 256, GEMM_SMEM>>>(bias2, out, 0, 1);   // #7
}